// round 14
// baseline (speedup 1.0000x reference)
#include <cuda_runtime.h>

#define NN 1024
#define NB 8

// ---------------- scratch (static device globals: allowed) ----------------
// Zero-initialized at module load; k_redfinal's tail resets them per replay.
static __device__ float  g_C[NB * NN];    // per-batch Tref column sums
static __device__ float  g_R[NB * NN];    // per-batch Tref row sums
static __device__ float2 g_sf[NN];        // 1.5 * shift factor per element j
static __device__ float2 g_twtab[32 * 32];// twtab[c*32+lane] = exp(-2pi i lane c/1024)
static __device__ float  g_ctm[NN];       // column sums of spectrogram
static __device__ double g_smm;           // sum(Tmeas^2)
static __device__ int    g_maxbits;       // max(Tmeas) as int bits (values >= 0)
static __device__ double g_smt[NB], g_stt[NB];

// 5-bit bit reversal of a compile-time-constant p
#define BR5(p) ((((p)&1)<<4)|(((p)&2)<<2)|((p)&4)|(((p)&8)>>2)|(((p)&16)>>4))

// ---------------- register FFT32 (DIF, natural in, bit-reversed out) -------
#define BF(i0,i1,C,S) { float ax=vx[i0],ay=vy[i0],bx=vx[i1],by=vy[i1]; \
  vx[i0]=ax+bx; vy[i0]=ay+by; float dx=ax-bx,dy=ay-by;                 \
  vx[i1]=fmaf(dy,(S),dx*(C)); vy[i1]=fmaf(-dx,(S),dy*(C)); }
#define BF1(i0,i1) { float ax=vx[i0],ay=vy[i0],bx=vx[i1],by=vy[i1];    \
  vx[i0]=ax+bx; vy[i0]=ay+by; vx[i1]=ax-bx; vy[i1]=ay-by; }
#define BFI(i0,i1) { float ax=vx[i0],ay=vy[i0],bx=vx[i1],by=vy[i1];    \
  vx[i0]=ax+bx; vy[i0]=ay+by; float dx=ax-bx,dy=ay-by;                 \
  vx[i1]=dy; vy[i1]=-dx; }

__device__ __forceinline__ void fft32(float vx[32], float vy[32]) {
  BF1(0,16)
  BF(1,17, 0.98078528040323043f, 0.19509032201612825f)
  BF(2,18, 0.92387953251128674f, 0.38268343236508978f)
  BF(3,19, 0.83146961230254524f, 0.55557023301960218f)
  BF(4,20, 0.70710678118654757f, 0.70710678118654757f)
  BF(5,21, 0.55557023301960218f, 0.83146961230254524f)
  BF(6,22, 0.38268343236508978f, 0.92387953251128674f)
  BF(7,23, 0.19509032201612825f, 0.98078528040323043f)
  BFI(8,24)
  BF(9,25, -0.19509032201612825f, 0.98078528040323043f)
  BF(10,26,-0.38268343236508978f, 0.92387953251128674f)
  BF(11,27,-0.55557023301960218f, 0.83146961230254524f)
  BF(12,28,-0.70710678118654757f, 0.70710678118654757f)
  BF(13,29,-0.83146961230254524f, 0.55557023301960218f)
  BF(14,30,-0.92387953251128674f, 0.38268343236508978f)
  BF(15,31,-0.98078528040323043f, 0.19509032201612825f)
#pragma unroll
  for (int g = 0; g < 32; g += 16) {
    BF1(g+0, g+8)
    BF(g+1, g+9,  0.92387953251128674f, 0.38268343236508978f)
    BF(g+2, g+10, 0.70710678118654757f, 0.70710678118654757f)
    BF(g+3, g+11, 0.38268343236508978f, 0.92387953251128674f)
    BFI(g+4, g+12)
    BF(g+5, g+13,-0.38268343236508978f, 0.92387953251128674f)
    BF(g+6, g+14,-0.70710678118654757f, 0.70710678118654757f)
    BF(g+7, g+15,-0.92387953251128674f, 0.38268343236508978f)
  }
#pragma unroll
  for (int g = 0; g < 32; g += 8) {
    BF1(g+0, g+4)
    BF(g+1, g+5,  0.70710678118654757f, 0.70710678118654757f)
    BFI(g+2, g+6)
    BF(g+3, g+7, -0.70710678118654757f, 0.70710678118654757f)
  }
#pragma unroll
  for (int g = 0; g < 32; g += 4) {
    BF1(g+0, g+2)
    BFI(g+1, g+3)
  }
#pragma unroll
  for (int g = 0; g < 32; g += 2) {
    BF1(g, g+1)
  }
}

__device__ __forceinline__ float fsqrt_approx(float x) {
  float r;
  asm("sqrt.approx.f32 %0, %1;" : "=f"(r) : "f"(x));
  return r;
}

// ---------------- k_prep: tables only (idempotent, 4 blocks) ---------------
__global__ void k_prep() {
  int gid = blockIdx.x * 256 + threadIdx.x;   // 0..1023
  const float c32 = (float)(2.0 * 337.927 * 1.5);   // fl32(1013.781)
  float t = c32 * (float)(gid - NN / 2);            // fp32 product (as jnp)
  double s, c;
  sincos((double)t, &s, &c);
  g_sf[gid] = make_float2((float)(1.5 * c), (float)(-1.5 * s));
  {
    int ci = gid >> 5, lane = gid & 31;
    double th = (double)(ci * lane) * (6.283185307179586232e0 / 1024.0);
    double s2, c2;
    sincos(th, &s2, &c2);
    g_twtab[gid] = make_float2((float)c2, (float)(-s2));
  }
}

// ---- main: blocks 0..1023 = FFT rows; blocks 1024..1279 = tmeas stats -----
// Stats accumulators (g_ctm, g_smm, g_maxbits) are pre-zeroed (module load /
// k_redfinal tail). Consumers of stats are in the NEXT launch -> no race.
__global__ void __launch_bounds__(128) k_main(const float* __restrict__ pred,
                                              const float* __restrict__ tmeas) {
  int tid = threadIdx.x;

  if (blockIdx.x >= 1024) {
    // ---------- stats path: 256 blocks x 128 threads, 4 rows each ----------
    int r0 = (blockIdx.x - 1024) * 4;
    float cs[8];
#pragma unroll
    for (int k = 0; k < 8; ++k) cs[k] = 0.f;
    float sq = 0.f, mx = 0.f;
#pragma unroll
    for (int r = r0; r < r0 + 4; ++r) {
      const float* rowp = tmeas + (size_t)r * NN;
#pragma unroll
      for (int k = 0; k < 8; ++k) {
        float v = rowp[tid + 128 * k];
        cs[k] += v;
        sq = fmaf(v, v, sq);
        mx = fmaxf(mx, v);
      }
    }
#pragma unroll
    for (int k = 0; k < 8; ++k)
      atomicAdd(&g_ctm[tid + 128 * k], cs[k]);
#pragma unroll
    for (int o = 16; o; o >>= 1) {
      sq += __shfl_xor_sync(0xffffffffu, sq, o);
      mx = fmaxf(mx, __shfl_xor_sync(0xffffffffu, mx, o));
    }
    __shared__ float ssq[4], smx[4];
    int w = tid >> 5, l = tid & 31;
    if (l == 0) { ssq[w] = sq; smx[w] = mx; }
    __syncthreads();
    if (tid == 0) {
      float a = ssq[0] + ssq[1] + ssq[2] + ssq[3];
      float b2 = fmaxf(fmaxf(smx[0], smx[1]), fmaxf(smx[2], smx[3]));
      atomicAdd(&g_smm, (double)a);
      atomicMax(&g_maxbits, __float_as_int(b2));
    }
    return;
  }

  // ---------- FFT path: 2 rows per warp ----------
  __shared__ float2 sh2[4 * 1056];        // per-warp 32x33 complex transpose buf
  __shared__ float2 sy2[NN];              // batch analytic signal, interleaved
  int warp = tid >> 5, lane = tid & 31;
  int row0 = blockIdx.x * 8 + warp * 2;   // first of 2 rows for this warp
  int b = row0 >> 10;

  for (int i = tid; i < NN; i += 128)
    sy2[i] = make_float2(pred[b * 2 * NN + i], pred[b * 2 * NN + NN + i]);
  __syncthreads();

  float2* tb = sh2 + warp * 1056;

  float csum[32];
#pragma unroll
  for (int p = 0; p < 32; ++p) csum[p] = 0.f;
  float stt = 0.f, smt = 0.f;

#pragma unroll 1
  for (int r = 0; r < 2; ++r) {
    int m = (row0 & (NN - 1)) + r;
    int delay = m - NN / 2;

    float vx[32], vy[32];
#pragma unroll
    for (int a = 0; a < 32; ++a) {
      int j = a * 32 + lane;
      int jj = (j - delay) & (NN - 1);
      float2 ya = sy2[j];
      float2 yb = sy2[jj];
      float2 sf = g_sf[j];
      float prr = ya.x * yb.x - ya.y * yb.y;
      float pri = ya.x * yb.y + ya.y * yb.x;
      vx[a] = prr * sf.x - pri * sf.y;
      vy[a] = prr * sf.y + pri * sf.x;
    }
    fft32(vx, vy);

#pragma unroll
    for (int c = 0; c < 32; ++c) {
      int p = BR5(c);
      float2 w = g_twtab[c * 32 + lane];
      float x = vx[p], y = vy[p];
      vx[p] = x * w.x - y * w.y;
      vy[p] = x * w.y + y * w.x;
    }

#pragma unroll
    for (int p = 0; p < 32; ++p) {
      int c = BR5(p);
      tb[c * 33 + lane] = make_float2(vx[p], vy[p]);
    }
    __syncwarp();
#pragma unroll
    for (int bb = 0; bb < 32; ++bb) {
      float2 t2 = tb[lane * 33 + bb];
      vx[bb] = t2.x; vy[bb] = t2.y;
    }
    __syncwarp();
    fft32(vx, vy);

    float rsum = 0.f;
    const float* tmr = tmeas + (size_t)m * NN;
#pragma unroll
    for (int p = 0; p < 32; ++p) {
      int col = lane + ((BR5(p) ^ 16) << 5);
      float mag = fsqrt_approx(fmaf(vx[p], vx[p], vy[p] * vy[p]));
      csum[p] += mag;
      rsum += mag;
      stt = fmaf(mag, mag, stt);
      smt = fmaf(tmr[col], mag, smt);
    }
#pragma unroll
    for (int o = 16; o; o >>= 1)
      rsum += __shfl_xor_sync(0xffffffffu, rsum, o);
    if (lane == 0) g_R[row0 + r] = rsum;
  }

#pragma unroll
  for (int o = 16; o; o >>= 1) {
    stt += __shfl_xor_sync(0xffffffffu, stt, o);
    smt += __shfl_xor_sync(0xffffffffu, smt, o);
  }
  if (lane == 0) {
    atomicAdd(&g_smt[b], (double)smt);
    atomicAdd(&g_stt[b], (double)stt);
  }

  // combine 4 warps' column sums in shared, then one atomic add per column
  __syncthreads();
  float* sflat = (float*)sh2;
#pragma unroll
  for (int p = 0; p < 32; ++p) {
    int col = lane + ((BR5(p) ^ 16) << 5);
    sflat[warp * 1024 + col] = csum[p];
  }
  __syncthreads();
  float* cb = g_C + b * NN;
#pragma unroll
  for (int k = 0; k < 8; ++k) {
    int col = tid + 128 * k;
    float v = sflat[col] + sflat[1024 + col] + sflat[2048 + col] + sflat[3072 + col];
    atomicAdd(&cb[col], v);
  }
}

// ---- fused: den/num dots + frog error + output + accumulator reset --------
__global__ void k_redfinal(float* __restrict__ out) {
  __shared__ double sd[NB], sn[NB];
  int tid = threadIdx.x;                  // 1024 threads, 1 block
  int w = tid >> 5, lane = tid & 31;
  int b = w >> 2;                         // 4 warps per batch
  int base = (w & 3) * 256 + lane;

  if (tid < NB) { sd[tid] = 0.0; sn[tid] = 0.0; }
  __syncthreads();

  float sden = 0.f, snum = 0.f;
#pragma unroll
  for (int k = 0; k < 8; ++k) {
    int idx = base + 32 * k;
    float r = g_R[b * NN + idx];
    sden = fmaf(g_C[b * NN + idx], r, sden);
    snum = fmaf(g_ctm[idx], r, snum);
  }
#pragma unroll
  for (int o = 16; o; o >>= 1) {
    sden += __shfl_xor_sync(0xffffffffu, sden, o);
    snum += __shfl_xor_sync(0xffffffffu, snum, o);
  }
  if (lane == 0) {
    atomicAdd(&sd[b], (double)sden);
    atomicAdd(&sn[b], (double)snum);
  }
  __syncthreads();

  // threads 0..7: parallel per-batch scalar math (2 DDIVs deep), then reduce
  double e = 0.0;
  if (tid < NB) {
    float mx = __int_as_float(g_maxbits);
    double inv_norm = 1.0 / (1048576.0 * (double)mx * (double)mx);
    double mu = sn[tid] / sd[tid];
    double r = g_smm - 2.0 * mu * g_smt[tid] + mu * mu * g_stt[tid];
    if (r < 0.0) r = 0.0;
    e = (double)sqrtf((float)(r * inv_norm));
  }
  if (tid < 32) {
#pragma unroll
    for (int o = 4; o; o >>= 1)
      e += __shfl_down_sync(0xffffffffu, e, o);
    if (tid == 0) out[0] = (float)(e / (double)NB);
  }
  __syncthreads();                        // output computed before reset

  // reset accumulators for the next graph replay
#pragma unroll
  for (int i = 0; i < NB; ++i) g_C[tid + i * NN] = 0.0f;
  g_ctm[tid] = 0.0f;
  if (tid < NB) { g_smt[tid] = 0.0; g_stt[tid] = 0.0; }
  if (tid == 0) { g_smm = 0.0; g_maxbits = 0; }
}

extern "C" void kernel_launch(void* const* d_in, const int* in_sizes, int n_in,
                              void* d_out, int out_size) {
  const float* pred  = (const float*)d_in[0];   // [8, 2048]
  // d_in[1] = label, unused by the reference loss
  const float* tmeas = (const float*)d_in[2];   // [1024, 1024]
  (void)in_sizes; (void)n_in; (void)out_size;

  k_prep<<<4, 256>>>();
  k_main<<<1280, 128>>>(pred, tmeas);
  k_redfinal<<<1, 1024>>>((float*)d_out);
}

// round 15
// speedup vs baseline: 1.1032x; 1.1032x over previous
#include <cuda_runtime.h>

#define NN 1024
#define NB 8

// ---------------- scratch (static device globals: allowed) ----------------
// Zero-initialized at module load; k_redfinal's tail resets them per replay.
static __device__ float  g_C[NB * NN];    // per-batch Tref column sums
static __device__ float  g_R[NB * NN];    // per-batch Tref row sums
static __device__ float2 g_sf[NN];        // 1.5 * shift factor per element j
static __device__ float2 g_twtab[32 * 32];// twtab[c*32+lane] = exp(-2pi i lane c/1024)
static __device__ float  g_ctm[NN];       // column sums of spectrogram
static __device__ double g_smm;           // sum(Tmeas^2)
static __device__ int    g_maxbits;       // max(Tmeas) as int bits (values >= 0)
static __device__ double g_smt[NB], g_stt[NB];

// 5-bit bit reversal of a compile-time-constant p
#define BR5(p) ((((p)&1)<<4)|(((p)&2)<<2)|((p)&4)|(((p)&8)>>2)|(((p)&16)>>4))

// ---------------- register FFT32 (DIF, natural in, bit-reversed out) -------
#define BF(i0,i1,C,S) { float ax=vx[i0],ay=vy[i0],bx=vx[i1],by=vy[i1]; \
  vx[i0]=ax+bx; vy[i0]=ay+by; float dx=ax-bx,dy=ay-by;                 \
  vx[i1]=fmaf(dy,(S),dx*(C)); vy[i1]=fmaf(-dx,(S),dy*(C)); }
#define BF1(i0,i1) { float ax=vx[i0],ay=vy[i0],bx=vx[i1],by=vy[i1];    \
  vx[i0]=ax+bx; vy[i0]=ay+by; vx[i1]=ax-bx; vy[i1]=ay-by; }
#define BFI(i0,i1) { float ax=vx[i0],ay=vy[i0],bx=vx[i1],by=vy[i1];    \
  vx[i0]=ax+bx; vy[i0]=ay+by; float dx=ax-bx,dy=ay-by;                 \
  vx[i1]=dy; vy[i1]=-dx; }

__device__ __forceinline__ void fft32(float vx[32], float vy[32]) {
  BF1(0,16)
  BF(1,17, 0.98078528040323043f, 0.19509032201612825f)
  BF(2,18, 0.92387953251128674f, 0.38268343236508978f)
  BF(3,19, 0.83146961230254524f, 0.55557023301960218f)
  BF(4,20, 0.70710678118654757f, 0.70710678118654757f)
  BF(5,21, 0.55557023301960218f, 0.83146961230254524f)
  BF(6,22, 0.38268343236508978f, 0.92387953251128674f)
  BF(7,23, 0.19509032201612825f, 0.98078528040323043f)
  BFI(8,24)
  BF(9,25, -0.19509032201612825f, 0.98078528040323043f)
  BF(10,26,-0.38268343236508978f, 0.92387953251128674f)
  BF(11,27,-0.55557023301960218f, 0.83146961230254524f)
  BF(12,28,-0.70710678118654757f, 0.70710678118654757f)
  BF(13,29,-0.83146961230254524f, 0.55557023301960218f)
  BF(14,30,-0.92387953251128674f, 0.38268343236508978f)
  BF(15,31,-0.98078528040323043f, 0.19509032201612825f)
#pragma unroll
  for (int g = 0; g < 32; g += 16) {
    BF1(g+0, g+8)
    BF(g+1, g+9,  0.92387953251128674f, 0.38268343236508978f)
    BF(g+2, g+10, 0.70710678118654757f, 0.70710678118654757f)
    BF(g+3, g+11, 0.38268343236508978f, 0.92387953251128674f)
    BFI(g+4, g+12)
    BF(g+5, g+13,-0.38268343236508978f, 0.92387953251128674f)
    BF(g+6, g+14,-0.70710678118654757f, 0.70710678118654757f)
    BF(g+7, g+15,-0.92387953251128674f, 0.38268343236508978f)
  }
#pragma unroll
  for (int g = 0; g < 32; g += 8) {
    BF1(g+0, g+4)
    BF(g+1, g+5,  0.70710678118654757f, 0.70710678118654757f)
    BFI(g+2, g+6)
    BF(g+3, g+7, -0.70710678118654757f, 0.70710678118654757f)
  }
#pragma unroll
  for (int g = 0; g < 32; g += 4) {
    BF1(g+0, g+2)
    BFI(g+1, g+3)
  }
#pragma unroll
  for (int g = 0; g < 32; g += 2) {
    BF1(g, g+1)
  }
}

__device__ __forceinline__ float fsqrt_approx(float x) {
  float r;
  asm("sqrt.approx.f32 %0, %1;" : "=f"(r) : "f"(x));
  return r;
}

// ---- k_prep: tables via sincospi (no range reduction), 1 entry/thread -----
// 2048 work items: [0,1024) = sf entries, [1024,2048) = twtab entries.
__global__ void k_prep() {
  int gid = blockIdx.x * 32 + threadIdx.x;    // 0..2047
  if (gid < NN) {
    // sf[j] = 1.5 * exp(-i * t),  t = fl32(1013.781) * (j - 512) in fp32,
    // evaluated as sinpi/cospi of (t / pi): |arg error| ~ t*eps/pi ~ 3.5e-11.
    const float c32 = (float)(2.0 * 337.927 * 1.5);   // fl32(1013.781)
    float t = c32 * (float)(gid - NN / 2);            // fp32 product (as jnp)
    double s, c;
    sincospi((double)t * 0.31830988618379067154, &s, &c);  // 1/pi
    g_sf[gid] = make_float2((float)(1.5 * c), (float)(-1.5 * s));
  } else {
    // twtab[c][lane] = exp(-2pi i c*lane/1024): angle = (c*lane/512) * pi
    int e = gid - NN;
    int ci = e >> 5, lane = e & 31;
    double s, c;
    sincospi((double)(ci * lane) * (1.0 / 512.0), &s, &c);
    g_twtab[e] = make_float2((float)c, (float)(-s));
  }
}

// ---- main: blocks 0..1023 = FFT rows; blocks 1024..1279 = tmeas stats -----
// Stats accumulators (g_ctm, g_smm, g_maxbits) are pre-zeroed (module load /
// k_redfinal tail). Consumers of stats are in the NEXT launch -> no race.
__global__ void __launch_bounds__(128) k_main(const float* __restrict__ pred,
                                              const float* __restrict__ tmeas) {
  int tid = threadIdx.x;

  if (blockIdx.x >= 1024) {
    // ---------- stats path: 256 blocks x 128 threads, 4 rows each ----------
    int r0 = (blockIdx.x - 1024) * 4;
    float cs[8];
#pragma unroll
    for (int k = 0; k < 8; ++k) cs[k] = 0.f;
    float sq = 0.f, mx = 0.f;
#pragma unroll
    for (int r = r0; r < r0 + 4; ++r) {
      const float* rowp = tmeas + (size_t)r * NN;
#pragma unroll
      for (int k = 0; k < 8; ++k) {
        float v = rowp[tid + 128 * k];
        cs[k] += v;
        sq = fmaf(v, v, sq);
        mx = fmaxf(mx, v);
      }
    }
#pragma unroll
    for (int k = 0; k < 8; ++k)
      atomicAdd(&g_ctm[tid + 128 * k], cs[k]);
#pragma unroll
    for (int o = 16; o; o >>= 1) {
      sq += __shfl_xor_sync(0xffffffffu, sq, o);
      mx = fmaxf(mx, __shfl_xor_sync(0xffffffffu, mx, o));
    }
    __shared__ float ssq[4], smx[4];
    int w = tid >> 5, l = tid & 31;
    if (l == 0) { ssq[w] = sq; smx[w] = mx; }
    __syncthreads();
    if (tid == 0) {
      float a = ssq[0] + ssq[1] + ssq[2] + ssq[3];
      float b2 = fmaxf(fmaxf(smx[0], smx[1]), fmaxf(smx[2], smx[3]));
      atomicAdd(&g_smm, (double)a);
      atomicMax(&g_maxbits, __float_as_int(b2));
    }
    return;
  }

  // ---------- FFT path: 2 rows per warp ----------
  __shared__ float2 sh2[4 * 1056];        // per-warp 32x33 complex transpose buf
  __shared__ float2 sy2[NN];              // batch analytic signal, interleaved
  int warp = tid >> 5, lane = tid & 31;
  int row0 = blockIdx.x * 8 + warp * 2;   // first of 2 rows for this warp
  int b = row0 >> 10;

  for (int i = tid; i < NN; i += 128)
    sy2[i] = make_float2(pred[b * 2 * NN + i], pred[b * 2 * NN + NN + i]);
  __syncthreads();

  float2* tb = sh2 + warp * 1056;

  float csum[32];
#pragma unroll
  for (int p = 0; p < 32; ++p) csum[p] = 0.f;
  float stt = 0.f, smt = 0.f;

#pragma unroll 1
  for (int r = 0; r < 2; ++r) {
    int m = (row0 & (NN - 1)) + r;
    int delay = m - NN / 2;

    float vx[32], vy[32];
#pragma unroll
    for (int a = 0; a < 32; ++a) {
      int j = a * 32 + lane;
      int jj = (j - delay) & (NN - 1);
      float2 ya = sy2[j];
      float2 yb = sy2[jj];
      float2 sf = g_sf[j];
      float prr = ya.x * yb.x - ya.y * yb.y;
      float pri = ya.x * yb.y + ya.y * yb.x;
      vx[a] = prr * sf.x - pri * sf.y;
      vy[a] = prr * sf.y + pri * sf.x;
    }
    fft32(vx, vy);

#pragma unroll
    for (int c = 0; c < 32; ++c) {
      int p = BR5(c);
      float2 w = g_twtab[c * 32 + lane];
      float x = vx[p], y = vy[p];
      vx[p] = x * w.x - y * w.y;
      vy[p] = x * w.y + y * w.x;
    }

#pragma unroll
    for (int p = 0; p < 32; ++p) {
      int c = BR5(p);
      tb[c * 33 + lane] = make_float2(vx[p], vy[p]);
    }
    __syncwarp();
#pragma unroll
    for (int bb = 0; bb < 32; ++bb) {
      float2 t2 = tb[lane * 33 + bb];
      vx[bb] = t2.x; vy[bb] = t2.y;
    }
    __syncwarp();
    fft32(vx, vy);

    float rsum = 0.f;
    const float* tmr = tmeas + (size_t)m * NN;
#pragma unroll
    for (int p = 0; p < 32; ++p) {
      int col = lane + ((BR5(p) ^ 16) << 5);
      float mag = fsqrt_approx(fmaf(vx[p], vx[p], vy[p] * vy[p]));
      csum[p] += mag;
      rsum += mag;
      stt = fmaf(mag, mag, stt);
      smt = fmaf(tmr[col], mag, smt);
    }
#pragma unroll
    for (int o = 16; o; o >>= 1)
      rsum += __shfl_xor_sync(0xffffffffu, rsum, o);
    if (lane == 0) g_R[row0 + r] = rsum;
  }

#pragma unroll
  for (int o = 16; o; o >>= 1) {
    stt += __shfl_xor_sync(0xffffffffu, stt, o);
    smt += __shfl_xor_sync(0xffffffffu, smt, o);
  }
  if (lane == 0) {
    atomicAdd(&g_smt[b], (double)smt);
    atomicAdd(&g_stt[b], (double)stt);
  }

  // combine 4 warps' column sums in shared, then one atomic add per column
  __syncthreads();
  float* sflat = (float*)sh2;
#pragma unroll
  for (int p = 0; p < 32; ++p) {
    int col = lane + ((BR5(p) ^ 16) << 5);
    sflat[warp * 1024 + col] = csum[p];
  }
  __syncthreads();
  float* cb = g_C + b * NN;
#pragma unroll
  for (int k = 0; k < 8; ++k) {
    int col = tid + 128 * k;
    float v = sflat[col] + sflat[1024 + col] + sflat[2048 + col] + sflat[3072 + col];
    atomicAdd(&cb[col], v);
  }
}

// ---- fused: den/num dots + frog error + output + accumulator reset --------
__global__ void k_redfinal(float* __restrict__ out) {
  __shared__ double sd[NB], sn[NB];
  int tid = threadIdx.x;                  // 1024 threads, 1 block
  int w = tid >> 5, lane = tid & 31;
  int b = w >> 2;                         // 4 warps per batch
  int base = (w & 3) * 256 + lane;

  if (tid < NB) { sd[tid] = 0.0; sn[tid] = 0.0; }
  __syncthreads();

  float sden = 0.f, snum = 0.f;
#pragma unroll
  for (int k = 0; k < 8; ++k) {
    int idx = base + 32 * k;
    float r = g_R[b * NN + idx];
    sden = fmaf(g_C[b * NN + idx], r, sden);
    snum = fmaf(g_ctm[idx], r, snum);
  }
#pragma unroll
  for (int o = 16; o; o >>= 1) {
    sden += __shfl_xor_sync(0xffffffffu, sden, o);
    snum += __shfl_xor_sync(0xffffffffu, snum, o);
  }
  if (lane == 0) {
    atomicAdd(&sd[b], (double)sden);
    atomicAdd(&sn[b], (double)snum);
  }
  __syncthreads();

  // threads 0..7: parallel per-batch scalar math (2 DDIVs deep), then reduce
  double e = 0.0;
  if (tid < NB) {
    float mx = __int_as_float(g_maxbits);
    double inv_norm = 1.0 / (1048576.0 * (double)mx * (double)mx);
    double mu = sn[tid] / sd[tid];
    double r = g_smm - 2.0 * mu * g_smt[tid] + mu * mu * g_stt[tid];
    if (r < 0.0) r = 0.0;
    e = (double)sqrtf((float)(r * inv_norm));
  }
  if (tid < 32) {
#pragma unroll
    for (int o = 4; o; o >>= 1)
      e += __shfl_down_sync(0xffffffffu, e, o);
    if (tid == 0) out[0] = (float)(e / (double)NB);
  }
  __syncthreads();                        // output computed before reset

  // reset accumulators for the next graph replay
#pragma unroll
  for (int i = 0; i < NB; ++i) g_C[tid + i * NN] = 0.0f;
  g_ctm[tid] = 0.0f;
  if (tid < NB) { g_smt[tid] = 0.0; g_stt[tid] = 0.0; }
  if (tid == 0) { g_smm = 0.0; g_maxbits = 0; }
}

extern "C" void kernel_launch(void* const* d_in, const int* in_sizes, int n_in,
                              void* d_out, int out_size) {
  const float* pred  = (const float*)d_in[0];   // [8, 2048]
  // d_in[1] = label, unused by the reference loss
  const float* tmeas = (const float*)d_in[2];   // [1024, 1024]
  (void)in_sizes; (void)n_in; (void)out_size;

  k_prep<<<64, 32>>>();
  k_main<<<1280, 128>>>(pred, tmeas);
  k_redfinal<<<1, 1024>>>((float*)d_out);
}

// round 16
// speedup vs baseline: 1.1041x; 1.0008x over previous
#include <cuda_runtime.h>

#define NN 1024
#define NB 8

// ---------------- scratch (static device globals: allowed) ----------------
// Zero-initialized at module load; k_redfinal's tail resets them per replay.
static __device__ float  g_C[NB * NN];    // per-batch Tref column sums
static __device__ float  g_R[NB * NN];    // per-batch Tref row sums
static __device__ float2 g_sf[NN];        // 1.5 * shift factor per element j
static __device__ float2 g_twtab[32 * 32];// twtab[c*32+lane] = exp(-2pi i lane c/1024)
static __device__ float  g_ctm[NN];       // column sums of spectrogram
static __device__ double g_smm;           // sum(Tmeas^2)
static __device__ int    g_maxbits;       // max(Tmeas) as int bits (values >= 0)
static __device__ double g_smt[NB], g_stt[NB];

// 5-bit bit reversal of a compile-time-constant p
#define BR5(p) ((((p)&1)<<4)|(((p)&2)<<2)|((p)&4)|(((p)&8)>>2)|(((p)&16)>>4))

// ---------------- register FFT32 (DIF, natural in, bit-reversed out) -------
#define BF(i0,i1,C,S) { float ax=vx[i0],ay=vy[i0],bx=vx[i1],by=vy[i1]; \
  vx[i0]=ax+bx; vy[i0]=ay+by; float dx=ax-bx,dy=ay-by;                 \
  vx[i1]=fmaf(dy,(S),dx*(C)); vy[i1]=fmaf(-dx,(S),dy*(C)); }
#define BF1(i0,i1) { float ax=vx[i0],ay=vy[i0],bx=vx[i1],by=vy[i1];    \
  vx[i0]=ax+bx; vy[i0]=ay+by; vx[i1]=ax-bx; vy[i1]=ay-by; }
#define BFI(i0,i1) { float ax=vx[i0],ay=vy[i0],bx=vx[i1],by=vy[i1];    \
  vx[i0]=ax+bx; vy[i0]=ay+by; float dx=ax-bx,dy=ay-by;                 \
  vx[i1]=dy; vy[i1]=-dx; }

__device__ __forceinline__ void fft32(float vx[32], float vy[32]) {
  BF1(0,16)
  BF(1,17, 0.98078528040323043f, 0.19509032201612825f)
  BF(2,18, 0.92387953251128674f, 0.38268343236508978f)
  BF(3,19, 0.83146961230254524f, 0.55557023301960218f)
  BF(4,20, 0.70710678118654757f, 0.70710678118654757f)
  BF(5,21, 0.55557023301960218f, 0.83146961230254524f)
  BF(6,22, 0.38268343236508978f, 0.92387953251128674f)
  BF(7,23, 0.19509032201612825f, 0.98078528040323043f)
  BFI(8,24)
  BF(9,25, -0.19509032201612825f, 0.98078528040323043f)
  BF(10,26,-0.38268343236508978f, 0.92387953251128674f)
  BF(11,27,-0.55557023301960218f, 0.83146961230254524f)
  BF(12,28,-0.70710678118654757f, 0.70710678118654757f)
  BF(13,29,-0.83146961230254524f, 0.55557023301960218f)
  BF(14,30,-0.92387953251128674f, 0.38268343236508978f)
  BF(15,31,-0.98078528040323043f, 0.19509032201612825f)
#pragma unroll
  for (int g = 0; g < 32; g += 16) {
    BF1(g+0, g+8)
    BF(g+1, g+9,  0.92387953251128674f, 0.38268343236508978f)
    BF(g+2, g+10, 0.70710678118654757f, 0.70710678118654757f)
    BF(g+3, g+11, 0.38268343236508978f, 0.92387953251128674f)
    BFI(g+4, g+12)
    BF(g+5, g+13,-0.38268343236508978f, 0.92387953251128674f)
    BF(g+6, g+14,-0.70710678118654757f, 0.70710678118654757f)
    BF(g+7, g+15,-0.92387953251128674f, 0.38268343236508978f)
  }
#pragma unroll
  for (int g = 0; g < 32; g += 8) {
    BF1(g+0, g+4)
    BF(g+1, g+5,  0.70710678118654757f, 0.70710678118654757f)
    BFI(g+2, g+6)
    BF(g+3, g+7, -0.70710678118654757f, 0.70710678118654757f)
  }
#pragma unroll
  for (int g = 0; g < 32; g += 4) {
    BF1(g+0, g+2)
    BFI(g+1, g+3)
  }
#pragma unroll
  for (int g = 0; g < 32; g += 2) {
    BF1(g, g+1)
  }
}

__device__ __forceinline__ float fsqrt_approx(float x) {
  float r;
  asm("sqrt.approx.f32 %0, %1;" : "=f"(r) : "f"(x));
  return r;
}

// ---- k_prep: tables, fp32 sincos after a 2-op double range reduction ------
// 2048 work items: [0,1024) = sf entries, [1024,2048) = twtab entries.
__global__ void k_prep() {
  int gid = blockIdx.x * 32 + threadIdx.x;    // 0..2047
  if (gid < NN) {
    // sf[j] = 1.5 * exp(-i*t), t = fl32(1013.781)*(j-512) (fp32, as jnp).
    // Reduce in double (1 DMUL + rint + sub: arg err ~1e-11 turns), then
    // fp32 sincos on |ang| <= pi (fast path). Total angle err ~3e-7 rad.
    const float c32 = (float)(2.0 * 337.927 * 1.5);   // fl32(1013.781)
    float t = c32 * (float)(gid - NN / 2);
    double d = (double)t * 0.15915494309189533577;    // t / (2*pi), in turns
    float f = (float)(d - rint(d));                   // [-0.5, 0.5] turns
    float ang = f * 6.28318530717958647692f;
    float s, c;
    sincosf(ang, &s, &c);
    g_sf[gid] = make_float2(1.5f * c, -1.5f * s);
  } else {
    // twtab[c][lane] = exp(-2pi i c*lane/1024). c*lane <= 961 is exact in
    // fp32; /1024 is exact; wrap to [-0.5,0.5] turns; fp32 sincos.
    int e = gid - NN;
    int ci = e >> 5, lane = e & 31;
    float f = (float)(ci * lane) * (1.0f / 1024.0f);
    f -= rintf(f);
    float ang = f * 6.28318530717958647692f;
    float s, c;
    sincosf(ang, &s, &c);
    g_twtab[e] = make_float2(c, -s);
  }
}

// ---- main: blocks 0..1023 = FFT rows; blocks 1024..1279 = tmeas stats -----
// Stats accumulators (g_ctm, g_smm, g_maxbits) are pre-zeroed (module load /
// k_redfinal tail). Consumers of stats are in the NEXT launch -> no race.
__global__ void __launch_bounds__(128) k_main(const float* __restrict__ pred,
                                              const float* __restrict__ tmeas) {
  int tid = threadIdx.x;

  if (blockIdx.x >= 1024) {
    // ---------- stats path: 256 blocks x 128 threads, 4 rows each ----------
    int r0 = (blockIdx.x - 1024) * 4;
    float cs[8];
#pragma unroll
    for (int k = 0; k < 8; ++k) cs[k] = 0.f;
    float sq = 0.f, mx = 0.f;
#pragma unroll
    for (int r = r0; r < r0 + 4; ++r) {
      const float* rowp = tmeas + (size_t)r * NN;
#pragma unroll
      for (int k = 0; k < 8; ++k) {
        float v = rowp[tid + 128 * k];
        cs[k] += v;
        sq = fmaf(v, v, sq);
        mx = fmaxf(mx, v);
      }
    }
#pragma unroll
    for (int k = 0; k < 8; ++k)
      atomicAdd(&g_ctm[tid + 128 * k], cs[k]);
#pragma unroll
    for (int o = 16; o; o >>= 1) {
      sq += __shfl_xor_sync(0xffffffffu, sq, o);
      mx = fmaxf(mx, __shfl_xor_sync(0xffffffffu, mx, o));
    }
    __shared__ float ssq[4], smx[4];
    int w = tid >> 5, l = tid & 31;
    if (l == 0) { ssq[w] = sq; smx[w] = mx; }
    __syncthreads();
    if (tid == 0) {
      float a = ssq[0] + ssq[1] + ssq[2] + ssq[3];
      float b2 = fmaxf(fmaxf(smx[0], smx[1]), fmaxf(smx[2], smx[3]));
      atomicAdd(&g_smm, (double)a);
      atomicMax(&g_maxbits, __float_as_int(b2));
    }
    return;
  }

  // ---------- FFT path: 2 rows per warp ----------
  __shared__ float2 sh2[4 * 1056];        // per-warp 32x33 complex transpose buf
  __shared__ float2 sy2[NN];              // batch analytic signal, interleaved
  int warp = tid >> 5, lane = tid & 31;
  int row0 = blockIdx.x * 8 + warp * 2;   // first of 2 rows for this warp
  int b = row0 >> 10;

  for (int i = tid; i < NN; i += 128)
    sy2[i] = make_float2(pred[b * 2 * NN + i], pred[b * 2 * NN + NN + i]);
  __syncthreads();

  float2* tb = sh2 + warp * 1056;

  float csum[32];
#pragma unroll
  for (int p = 0; p < 32; ++p) csum[p] = 0.f;
  float stt = 0.f, smt = 0.f;

#pragma unroll 1
  for (int r = 0; r < 2; ++r) {
    int m = (row0 & (NN - 1)) + r;
    int delay = m - NN / 2;

    float vx[32], vy[32];
#pragma unroll
    for (int a = 0; a < 32; ++a) {
      int j = a * 32 + lane;
      int jj = (j - delay) & (NN - 1);
      float2 ya = sy2[j];
      float2 yb = sy2[jj];
      float2 sf = g_sf[j];
      float prr = ya.x * yb.x - ya.y * yb.y;
      float pri = ya.x * yb.y + ya.y * yb.x;
      vx[a] = prr * sf.x - pri * sf.y;
      vy[a] = prr * sf.y + pri * sf.x;
    }
    fft32(vx, vy);

#pragma unroll
    for (int c = 0; c < 32; ++c) {
      int p = BR5(c);
      float2 w = g_twtab[c * 32 + lane];
      float x = vx[p], y = vy[p];
      vx[p] = x * w.x - y * w.y;
      vy[p] = x * w.y + y * w.x;
    }

#pragma unroll
    for (int p = 0; p < 32; ++p) {
      int c = BR5(p);
      tb[c * 33 + lane] = make_float2(vx[p], vy[p]);
    }
    __syncwarp();
#pragma unroll
    for (int bb = 0; bb < 32; ++bb) {
      float2 t2 = tb[lane * 33 + bb];
      vx[bb] = t2.x; vy[bb] = t2.y;
    }
    __syncwarp();
    fft32(vx, vy);

    float rsum = 0.f;
    const float* tmr = tmeas + (size_t)m * NN;
#pragma unroll
    for (int p = 0; p < 32; ++p) {
      int col = lane + ((BR5(p) ^ 16) << 5);
      float mag = fsqrt_approx(fmaf(vx[p], vx[p], vy[p] * vy[p]));
      csum[p] += mag;
      rsum += mag;
      stt = fmaf(mag, mag, stt);
      smt = fmaf(tmr[col], mag, smt);
    }
#pragma unroll
    for (int o = 16; o; o >>= 1)
      rsum += __shfl_xor_sync(0xffffffffu, rsum, o);
    if (lane == 0) g_R[row0 + r] = rsum;
  }

#pragma unroll
  for (int o = 16; o; o >>= 1) {
    stt += __shfl_xor_sync(0xffffffffu, stt, o);
    smt += __shfl_xor_sync(0xffffffffu, smt, o);
  }
  if (lane == 0) {
    atomicAdd(&g_smt[b], (double)smt);
    atomicAdd(&g_stt[b], (double)stt);
  }

  // combine 4 warps' column sums in shared, then one atomic add per column
  __syncthreads();
  float* sflat = (float*)sh2;
#pragma unroll
  for (int p = 0; p < 32; ++p) {
    int col = lane + ((BR5(p) ^ 16) << 5);
    sflat[warp * 1024 + col] = csum[p];
  }
  __syncthreads();
  float* cb = g_C + b * NN;
#pragma unroll
  for (int k = 0; k < 8; ++k) {
    int col = tid + 128 * k;
    float v = sflat[col] + sflat[1024 + col] + sflat[2048 + col] + sflat[3072 + col];
    atomicAdd(&cb[col], v);
  }
}

// ---- fused: den/num dots + frog error + output + accumulator reset --------
__global__ void k_redfinal(float* __restrict__ out) {
  __shared__ double sd[NB], sn[NB];
  int tid = threadIdx.x;                  // 1024 threads, 1 block
  int w = tid >> 5, lane = tid & 31;
  int b = w >> 2;                         // 4 warps per batch
  int base = (w & 3) * 256 + lane;

  if (tid < NB) { sd[tid] = 0.0; sn[tid] = 0.0; }
  __syncthreads();

  float sden = 0.f, snum = 0.f;
#pragma unroll
  for (int k = 0; k < 8; ++k) {
    int idx = base + 32 * k;
    float r = g_R[b * NN + idx];
    sden = fmaf(g_C[b * NN + idx], r, sden);
    snum = fmaf(g_ctm[idx], r, snum);
  }
#pragma unroll
  for (int o = 16; o; o >>= 1) {
    sden += __shfl_xor_sync(0xffffffffu, sden, o);
    snum += __shfl_xor_sync(0xffffffffu, snum, o);
  }
  if (lane == 0) {
    atomicAdd(&sd[b], (double)sden);
    atomicAdd(&sn[b], (double)snum);
  }
  __syncthreads();

  // threads 0..7: parallel per-batch scalar math (2 DDIVs deep), then reduce
  double e = 0.0;
  if (tid < NB) {
    float mx = __int_as_float(g_maxbits);
    double inv_norm = 1.0 / (1048576.0 * (double)mx * (double)mx);
    double mu = sn[tid] / sd[tid];
    double r = g_smm - 2.0 * mu * g_smt[tid] + mu * mu * g_stt[tid];
    if (r < 0.0) r = 0.0;
    e = (double)sqrtf((float)(r * inv_norm));
  }
  if (tid < 32) {
#pragma unroll
    for (int o = 4; o; o >>= 1)
      e += __shfl_down_sync(0xffffffffu, e, o);
    if (tid == 0) out[0] = (float)(e / (double)NB);
  }
  __syncthreads();                        // output computed before reset

  // reset accumulators for the next graph replay
#pragma unroll
  for (int i = 0; i < NB; ++i) g_C[tid + i * NN] = 0.0f;
  g_ctm[tid] = 0.0f;
  if (tid < NB) { g_smt[tid] = 0.0; g_stt[tid] = 0.0; }
  if (tid == 0) { g_smm = 0.0; g_maxbits = 0; }
}

extern "C" void kernel_launch(void* const* d_in, const int* in_sizes, int n_in,
                              void* d_out, int out_size) {
  const float* pred  = (const float*)d_in[0];   // [8, 2048]
  // d_in[1] = label, unused by the reference loss
  const float* tmeas = (const float*)d_in[2];   // [1024, 1024]
  (void)in_sizes; (void)n_in; (void)out_size;

  k_prep<<<64, 32>>>();
  k_main<<<1280, 128>>>(pred, tmeas);
  k_redfinal<<<1, 1024>>>((float*)d_out);
}